// round 1
// baseline (speedup 1.0000x reference)
#include <cuda_runtime.h>
#include <math.h>

// ---------------- scratch (device globals: allocation-free) ----------------
#define BS  4096          // B*S
#define D   1024
#define DFF 4096

__device__ float g_q  [BS * D];
__device__ float g_k  [BS * D];
__device__ float g_v  [BS * D];
__device__ float g_ctx[BS * D];
__device__ float g_t1 [BS * D];
__device__ float g_o1 [BS * D];
__device__ float g_o2 [BS * D];
__device__ float g_ff [BS * DFF];

// ---------------- GEMM: C[M,N] = A[M,K] @ B[K,N] + bias (+ReLU) -----------
// 128x128 block tile, BK=8, 256 threads, 8x8 per-thread microtile.
template <bool RELU>
__global__ __launch_bounds__(256) void sgemm_kernel(
    const float* __restrict__ A, const float* __restrict__ B,
    const float* __restrict__ bias, float* __restrict__ C,
    int M, int N, int K)
{
    __shared__ float As[8][128];
    __shared__ float Bs[8][128];

    const int tid  = threadIdx.x;
    const int tx   = tid & 15;
    const int ty   = tid >> 4;
    const int row0 = blockIdx.y * 128;
    const int col0 = blockIdx.x * 128;

    const int arow = tid >> 1;
    const int acol = (tid & 1) * 4;
    const int brow = tid >> 5;
    const int bcol = (tid & 31) * 4;

    const float* Ap = A + (size_t)(row0 + arow) * K + acol;
    const float* Bp = B + (size_t)brow * N + col0 + bcol;

    float acc[8][8];
    #pragma unroll
    for (int i = 0; i < 8; i++)
        #pragma unroll
        for (int j = 0; j < 8; j++) acc[i][j] = 0.f;

    for (int k0 = 0; k0 < K; k0 += 8) {
        float4 a  = *reinterpret_cast<const float4*>(Ap + k0);
        float4 b4 = *reinterpret_cast<const float4*>(Bp + (size_t)k0 * N);
        As[acol + 0][arow] = a.x;
        As[acol + 1][arow] = a.y;
        As[acol + 2][arow] = a.z;
        As[acol + 3][arow] = a.w;
        *reinterpret_cast<float4*>(&Bs[brow][bcol]) = b4;
        __syncthreads();

        #pragma unroll
        for (int kk = 0; kk < 8; kk++) {
            float ra[8], rb[8];
            #pragma unroll
            for (int i = 0; i < 8; i++) ra[i] = As[kk][ty * 8 + i];
            #pragma unroll
            for (int j = 0; j < 8; j++) rb[j] = Bs[kk][tx * 8 + j];
            #pragma unroll
            for (int i = 0; i < 8; i++)
                #pragma unroll
                for (int j = 0; j < 8; j++)
                    acc[i][j] = fmaf(ra[i], rb[j], acc[i][j]);
        }
        __syncthreads();
    }

    #pragma unroll
    for (int i = 0; i < 8; i++) {
        const int r = row0 + ty * 8 + i;
        #pragma unroll
        for (int j = 0; j < 8; j++) {
            const int c = col0 + tx * 8 + j;
            float v = acc[i][j] + bias[c];
            if (RELU) v = fmaxf(v, 0.f);
            C[(size_t)r * N + c] = v;
        }
    }
}

// ---------------- attention (flash-lite): per (b,h), 64 q-rows / block ----
// Q,K,V,O are [BS, D] with head h in columns [h*64, h*64+64).
__global__ __launch_bounds__(256) void attn_kernel(
    const float* __restrict__ Q, const float* __restrict__ K,
    const float* __restrict__ V, float* __restrict__ O, int causal)
{
    __shared__ float Qs[64][65];
    __shared__ float Ks[32][65];
    __shared__ float Vs[32][65];
    __shared__ float Ps[64][33];

    const int tid = threadIdx.x;
    const int tx  = tid & 15;   // 2 score cols / 4 out cols
    const int ty  = tid >> 4;   // 4 rows
    const int b   = blockIdx.x >> 4;
    const int h   = blockIdx.x & 15;
    const int q0  = blockIdx.y * 64;

    const size_t base = ((size_t)b * 1024) * D + (size_t)h * 64;
    const float* Qb = Q + base + (size_t)q0 * D;

    for (int i = tid; i < 64 * 64; i += 256) {
        const int r = i >> 6, c = i & 63;
        Qs[r][c] = Qb[(size_t)r * D + c];
    }

    float mx[4], lsum[4], acc[4][4];
    #pragma unroll
    for (int i = 0; i < 4; i++) {
        mx[i] = -1e30f; lsum[i] = 0.f;
        #pragma unroll
        for (int j = 0; j < 4; j++) acc[i][j] = 0.f;
    }

    const int nkt = causal ? (q0 + 64) / 32 : 32;
    for (int jt = 0; jt < nkt; jt++) {
        const int j0 = jt * 32;
        const float* Kb = K + base + (size_t)j0 * D;
        const float* Vb = V + base + (size_t)j0 * D;
        for (int i = tid; i < 32 * 64; i += 256) {
            const int r = i >> 6, c = i & 63;
            Ks[r][c] = Kb[(size_t)r * D + c];
            Vs[r][c] = Vb[(size_t)r * D + c];
        }
        __syncthreads();

        // scores: rows 4ty..4ty+3, cols 2tx..2tx+1
        float s[4][2];
        #pragma unroll
        for (int i = 0; i < 4; i++) { s[i][0] = 0.f; s[i][1] = 0.f; }
        #pragma unroll
        for (int kk = 0; kk < 64; kk++) {
            float qr[4];
            #pragma unroll
            for (int i = 0; i < 4; i++) qr[i] = Qs[4 * ty + i][kk];
            const float k0v = Ks[2 * tx + 0][kk];
            const float k1v = Ks[2 * tx + 1][kk];
            #pragma unroll
            for (int i = 0; i < 4; i++) {
                s[i][0] = fmaf(qr[i], k0v, s[i][0]);
                s[i][1] = fmaf(qr[i], k1v, s[i][1]);
            }
        }

        float fac[4];
        #pragma unroll
        for (int i = 0; i < 4; i++) {
            s[i][0] *= 0.125f;
            s[i][1] *= 0.125f;
            if (causal) {
                const int gq = q0 + 4 * ty + i;
                if (j0 + 2 * tx + 0 > gq) s[i][0] = -1e30f;
                if (j0 + 2 * tx + 1 > gq) s[i][1] = -1e30f;
            }
            float m = fmaxf(s[i][0], s[i][1]);
            #pragma unroll
            for (int o = 8; o > 0; o >>= 1)
                m = fmaxf(m, __shfl_xor_sync(0xffffffffu, m, o));
            const float mn = fmaxf(mx[i], m);
            fac[i] = __expf(mx[i] - mn);
            const float p0 = __expf(s[i][0] - mn);
            const float p1 = __expf(s[i][1] - mn);
            Ps[4 * ty + i][2 * tx + 0] = p0;
            Ps[4 * ty + i][2 * tx + 1] = p1;
            float rs = p0 + p1;
            #pragma unroll
            for (int o = 8; o > 0; o >>= 1)
                rs += __shfl_xor_sync(0xffffffffu, rs, o);
            lsum[i] = lsum[i] * fac[i] + rs;
            mx[i] = mn;
        }
        __syncthreads();

        #pragma unroll
        for (int i = 0; i < 4; i++)
            #pragma unroll
            for (int j = 0; j < 4; j++) acc[i][j] *= fac[i];

        #pragma unroll 8
        for (int jj = 0; jj < 32; jj++) {
            float pv[4], vv[4];
            #pragma unroll
            for (int i = 0; i < 4; i++) pv[i] = Ps[4 * ty + i][jj];
            #pragma unroll
            for (int j = 0; j < 4; j++) vv[j] = Vs[jj][4 * tx + j];
            #pragma unroll
            for (int i = 0; i < 4; i++)
                #pragma unroll
                for (int j = 0; j < 4; j++)
                    acc[i][j] = fmaf(pv[i], vv[j], acc[i][j]);
        }
        __syncthreads();
    }

    float* Ob = O + base + (size_t)q0 * D;
    #pragma unroll
    for (int i = 0; i < 4; i++) {
        const float inv = 1.f / lsum[i];
        #pragma unroll
        for (int j = 0; j < 4; j++)
            Ob[(size_t)(4 * ty + i) * D + 4 * tx + j] = acc[i][j] * inv;
    }
}

// ---------------- residual add + LayerNorm (one row per block) -------------
__device__ __forceinline__ float block_sum_256(float v, float* red)
{
    #pragma unroll
    for (int o = 16; o > 0; o >>= 1) v += __shfl_xor_sync(0xffffffffu, v, o);
    const int w = threadIdx.x >> 5;
    if ((threadIdx.x & 31) == 0) red[w] = v;
    __syncthreads();
    v = red[threadIdx.x & 7];
    #pragma unroll
    for (int o = 4; o > 0; o >>= 1) v += __shfl_xor_sync(0xffffffffu, v, o);
    __syncthreads();
    return v;
}

__global__ __launch_bounds__(256) void ln_kernel(
    const float* __restrict__ X, const float* __restrict__ Y,
    const float* __restrict__ g, const float* __restrict__ be,
    float* __restrict__ out)
{
    __shared__ float sm[D];
    __shared__ float red[8];
    const int row = blockIdx.x;
    const int tid = threadIdx.x;
    const float* x = X + (size_t)row * D;
    const float* y = Y + (size_t)row * D;

    float local = 0.f;
    #pragma unroll
    for (int i = tid; i < D; i += 256) {
        const float v = x[i] + y[i];
        sm[i] = v;
        local += v;
    }
    const float mean = block_sum_256(local, red) * (1.f / D);

    float lv = 0.f;
    #pragma unroll
    for (int i = tid; i < D; i += 256) {
        const float d = sm[i] - mean;
        lv += d * d;
    }
    const float var = block_sum_256(lv, red) * (1.f / D);
    const float rstd = rsqrtf(var + 1e-3f);

    #pragma unroll
    for (int i = tid; i < D; i += 256)
        out[(size_t)row * D + i] = (sm[i] - mean) * rstd * g[i] + be[i];
}

// ---------------- host orchestration ---------------------------------------
extern "C" void kernel_launch(void* const* d_in, const int* in_sizes, int n_in,
                              void* d_out, int out_size)
{
    const float* x   = (const float*)d_in[0];
    const float* enc = (const float*)d_in[1];

    const float *wq1, *bq1, *wk1, *bk1, *wv1, *bv1, *wo1, *bo1;
    const float *wq2, *bq2, *wk2, *bk2, *wv2, *bv2, *wo2, *bo2;
    const float *wff1, *bff1, *wff2, *bff2;
    const float *g1, *be1, *g2, *be2, *g3, *be3;

    if (in_sizes[3] == 1024) {
        // reference-signature order: wq1,bq1,wk1,bk1,...
        wq1 = (const float*)d_in[2];  bq1 = (const float*)d_in[3];
        wk1 = (const float*)d_in[4];  bk1 = (const float*)d_in[5];
        wv1 = (const float*)d_in[6];  bv1 = (const float*)d_in[7];
        wo1 = (const float*)d_in[8];  bo1 = (const float*)d_in[9];
        wq2 = (const float*)d_in[10]; bq2 = (const float*)d_in[11];
        wk2 = (const float*)d_in[12]; bk2 = (const float*)d_in[13];
        wv2 = (const float*)d_in[14]; bv2 = (const float*)d_in[15];
        wo2 = (const float*)d_in[16]; bo2 = (const float*)d_in[17];
    } else {
        // setup_inputs dict order: wq1,wk1,wv1,wo1,bq1,bk1,bv1,bo1,...
        wq1 = (const float*)d_in[2];  wk1 = (const float*)d_in[3];
        wv1 = (const float*)d_in[4];  wo1 = (const float*)d_in[5];
        bq1 = (const float*)d_in[6];  bk1 = (const float*)d_in[7];
        bv1 = (const float*)d_in[8];  bo1 = (const float*)d_in[9];
        wq2 = (const float*)d_in[10]; wk2 = (const float*)d_in[11];
        wv2 = (const float*)d_in[12]; wo2 = (const float*)d_in[13];
        bq2 = (const float*)d_in[14]; bk2 = (const float*)d_in[15];
        bv2 = (const float*)d_in[16]; bo2 = (const float*)d_in[17];
    }
    wff1 = (const float*)d_in[18]; bff1 = (const float*)d_in[19];
    wff2 = (const float*)d_in[20]; bff2 = (const float*)d_in[21];
    g1 = (const float*)d_in[22]; be1 = (const float*)d_in[23];
    g2 = (const float*)d_in[24]; be2 = (const float*)d_in[25];
    g3 = (const float*)d_in[26]; be3 = (const float*)d_in[27];

    float *q, *k, *v, *ctx, *t1, *o1, *o2, *ff;
    cudaGetSymbolAddress((void**)&q,   g_q);
    cudaGetSymbolAddress((void**)&k,   g_k);
    cudaGetSymbolAddress((void**)&v,   g_v);
    cudaGetSymbolAddress((void**)&ctx, g_ctx);
    cudaGetSymbolAddress((void**)&t1,  g_t1);
    cudaGetSymbolAddress((void**)&o1,  g_o1);
    cudaGetSymbolAddress((void**)&o2,  g_o2);
    cudaGetSymbolAddress((void**)&ff,  g_ff);

    const dim3 gD(D / 128, BS / 128);       // N=1024 GEMMs
    const dim3 gF1(DFF / 128, BS / 128);    // N=4096 GEMM
    const dim3 gAttn(64, 16);               // (B*H, S/64)

    // ---- self-attention block (causal) ----
    sgemm_kernel<false><<<gD, 256>>>(x, wq1, bq1, q, BS, D, D);
    sgemm_kernel<false><<<gD, 256>>>(x, wk1, bk1, k, BS, D, D);
    sgemm_kernel<false><<<gD, 256>>>(x, wv1, bv1, v, BS, D, D);
    attn_kernel<<<gAttn, 256>>>(q, k, v, ctx, 1);
    sgemm_kernel<false><<<gD, 256>>>(ctx, wo1, bo1, t1, BS, D, D);
    ln_kernel<<<BS, 256>>>(x, t1, g1, be1, o1);

    // ---- cross-attention block ----
    sgemm_kernel<false><<<gD, 256>>>(o1,  wq2, bq2, q, BS, D, D);
    sgemm_kernel<false><<<gD, 256>>>(enc, wk2, bk2, k, BS, D, D);
    sgemm_kernel<false><<<gD, 256>>>(enc, wv2, bv2, v, BS, D, D);
    attn_kernel<<<gAttn, 256>>>(q, k, v, ctx, 0);
    sgemm_kernel<false><<<gD, 256>>>(ctx, wo2, bo2, t1, BS, D, D);
    ln_kernel<<<BS, 256>>>(o1, t1, g2, be2, o2);

    // ---- FFN block ----
    sgemm_kernel<true ><<<gF1, 256>>>(o2, wff1, bff1, ff, BS, DFF, D);
    sgemm_kernel<false><<<gD, 256>>>(ff, wff2, bff2, t1, BS, D, DFF);
    ln_kernel<<<BS, 256>>>(o2, t1, g3, be3, (float*)d_out);

    (void)n_in; (void)out_size;
}